// round 1
// baseline (speedup 1.0000x reference)
#include <cuda_runtime.h>

#define E   300
#define P   5
#define H   200
#define S   256
#define L   34
#define B   8
#define KP  304          // K padded (300 -> 304)
#define NP  704          // N padded (702 -> 704)
#define M   (B*S)        // 2048
#define FCK (3*E + 2*H)  // 1300

// ---------------- scratch (static device globals; no allocations) ----------------
__device__ __align__(16) float d_A[M*KP];          // tok gathered, zero-padded K
__device__ __align__(16) float d_Wall[KP*NP];      // packed conv_tok taps + lexical FC slices
__device__ __align__(16) float d_Y[M*NP];          // GEMM output
__device__ __align__(16) float d_ct[M*H];          // conv_tok result, layout [b][j][h]
__device__ __align__(16) float d_g[H*512];         // conv_pf as function of d=j-i (interior)
__device__ __align__(16) float d_gB0[H*S];         // conv_pf at j=0   (per center i)
__device__ __align__(16) float d_gB255[H*S];       // conv_pf at j=255 (per center i)
__device__ __align__(16) float d_pool[M*2*H];      // [b][s][400] = [maxL | maxR]
__device__ __align__(16) float d_fcW2[2*H*L];      // fc_W[:, :400] transposed -> [c][l]
__device__ int d_is64;

// ---------------- int32/int64 input width detection ----------------
// int64 tokens (< VOCAB) have zero high words at odd int32 indices; int32 tokens
// almost surely have a nonzero odd-index word. Scan only words [0,2048) (safe both ways).
__global__ void detect_kernel(const int* in32) {
    __shared__ int any;
    if (threadIdx.x == 0) any = 0;
    __syncthreads();
    int local = 0;
    for (int t = threadIdx.x; t < 1024; t += blockDim.x)
        if (in32[2*t + 1] != 0) local = 1;
    if (local) atomicOr(&any, 1);
    __syncthreads();
    if (threadIdx.x == 0) d_is64 = (any == 0) ? 1 : 0;
}

// ---------------- gather token embeddings into padded A ----------------
__global__ void gather_kernel(const int* in32, const float* word_emb) {
    int row = blockIdx.x;                       // b*S + j
    long long tok = d_is64 ? ((const long long*)in32)[row]
                           : (long long)in32[row];
    const float* src = word_emb + tok * E;
    for (int e = threadIdx.x; e < KP; e += blockDim.x)
        d_A[row*KP + e] = (e < E) ? src[e] : 0.0f;
}

// ---------------- pack Wall[e][c] ----------------
// c <  600 : k=c/200, h=c%200 -> conv_W[h, e, k]
// c <  702 : cc=c-600, k=cc/34, l=cc%34 -> fc_W[l, 400 + k*300 + e]
__global__ void pack_wall_kernel(const float* conv_W, const float* fc_W) {
    int e = blockIdx.x;                          // 0..303
    for (int c = threadIdx.x; c < NP; c += blockDim.x) {
        float v = 0.0f;
        if (e < E) {
            if (c < 600) {
                int k = c / 200, h = c % 200;
                v = conv_W[h*((E+P)*3) + e*3 + k];
            } else if (c < 702) {
                int cc = c - 600, k = cc / L, l = cc % L;
                v = fc_W[l*FCK + 2*H + k*E + e];
            }
        }
        d_Wall[e*NP + c] = v;
    }
}

// ---------------- pack fcW2[c][l] = fc_W[l][c], c < 400 ----------------
__global__ void pack_fcw2_kernel(const float* fc_W) {
    int c = blockIdx.x;
    int l = threadIdx.x;
    if (l < L) d_fcW2[c*L + l] = fc_W[l*FCK + c];
}

// ---------------- position-feature conv tables ----------------
__global__ void gtables_kernel(const float* conv_W, const float* pf_emb) {
    int h = blockIdx.x;
    float w0[P], w1[P], w2[P];
    #pragma unroll
    for (int p = 0; p < P; p++) {
        const float* wp = conv_W + h*(E+P)*3 + (E+p)*3;
        w0[p] = wp[0]; w1[p] = wp[1]; w2[p] = wp[2];
    }
    int tid = threadIdx.x;
    for (int dd = tid; dd < 512; dd += blockDim.x) {
        int d = dd - 256;
        int i0 = abs(d-1); if (i0 > 255) i0 = 255;
        int i1 = abs(d);   if (i1 > 255) i1 = 255;
        int i2 = abs(d+1); if (i2 > 255) i2 = 255;
        float acc = 0.0f;
        #pragma unroll
        for (int p = 0; p < P; p++)
            acc += w0[p]*pf_emb[i0*P+p] + w1[p]*pf_emb[i1*P+p] + w2[p]*pf_emb[i2*P+p];
        d_g[h*512 + dd] = acc;
    }
    if (tid >= 1 && tid <= 254) {
        int i = tid;
        float a0 = 0.0f, a255 = 0.0f;
        #pragma unroll
        for (int p = 0; p < P; p++) {
            // j=0: inputs pf[i,0]=pf_emb[i], pf[i,1]=pf_emb[i-1]; left pad missing
            a0   += w1[p]*pf_emb[i*P+p]       + w2[p]*pf_emb[(i-1)*P+p];
            // j=255: inputs pf[i,254]=pf_emb[254-i? ->|254-i|], pf[i,255]=pf_emb[255-i]; right pad missing
            a255 += w0[p]*pf_emb[(254-i >= 0 ? 254-i : i-254)*P+p] + w1[p]*pf_emb[(255-i)*P+p];
        }
        d_gB0[h*S + i]   = a0;
        d_gB255[h*S + i] = a255;
    }
}

// ---------------- GEMM: Y[m][n] = sum_k A[m][k] * Wall[k][n] ----------------
// M=2048, N=704, K=304. Block tile 128x64, BK=16, 256 threads, 8x4 microtile.
__global__ __launch_bounds__(256) void gemm_kernel() {
    __shared__ float As[16][128];
    __shared__ float Bs[16][64];
    int mt = blockIdx.x;        // 16 tiles
    int nt = blockIdx.y;        // 11 tiles
    int t  = threadIdx.x;
    int tm = (t >> 4) * 8;      // 0..120
    int tn = (t & 15) * 4;      // 0..60

    float acc[8][4];
    #pragma unroll
    for (int i = 0; i < 8; i++)
        #pragma unroll
        for (int j = 0; j < 4; j++) acc[i][j] = 0.0f;

    const float* Ag = d_A + (mt*128)*KP;
    const float* Bg = d_Wall + nt*64;

    for (int kc = 0; kc < KP; kc += 16) {
        // load A tile (transposed into smem)
        {
            int idx = t;
            #pragma unroll
            for (int r = 0; r < 2; r++, idx += 256) {
                int m = idx >> 2, k4 = (idx & 3) * 4;
                float4 v = *(const float4*)(Ag + m*KP + kc + k4);
                As[k4+0][m] = v.x; As[k4+1][m] = v.y;
                As[k4+2][m] = v.z; As[k4+3][m] = v.w;
            }
            int k = t >> 4, n = (t & 15) * 4;
            float4 w = *(const float4*)(Bg + (kc + k)*NP + n);
            *(float4*)&Bs[k][n] = w;
        }
        __syncthreads();
        #pragma unroll
        for (int k = 0; k < 16; k++) {
            float a[8], bb[4];
            *(float4*)&a[0] = *(const float4*)&As[k][tm];
            *(float4*)&a[4] = *(const float4*)&As[k][tm+4];
            *(float4*)&bb[0] = *(const float4*)&Bs[k][tn];
            #pragma unroll
            for (int i = 0; i < 8; i++)
                #pragma unroll
                for (int j = 0; j < 4; j++)
                    acc[i][j] += a[i] * bb[j];
        }
        __syncthreads();
    }
    float* Yg = d_Y + (mt*128 + tm)*NP + nt*64 + tn;
    #pragma unroll
    for (int i = 0; i < 8; i++) {
        float4 v = make_float4(acc[i][0], acc[i][1], acc[i][2], acc[i][3]);
        *(float4*)(Yg + i*NP) = v;
    }
}

// ---------------- assemble conv_tok: ct[b][j][h] ----------------
__global__ void ct_kernel(const float* conv_b) {
    int row = blockIdx.x;            // b*S + j
    int j = row & (S-1);
    int h = threadIdx.x;
    if (h >= H) return;
    float v = conv_b[h] + d_Y[row*NP + 200 + h];
    if (j > 0)     v += d_Y[(row-1)*NP + h];
    if (j < S-1)   v += d_Y[(row+1)*NP + 400 + h];
    d_ct[row*H + h] = v;
}

// ---------------- max-plus pooling ----------------
// block = (h, b); lane t -> center i = t+1; loop j, split left/right by j < i.
__global__ __launch_bounds__(256) void pool_kernel() {
    int h = blockIdx.x, b = blockIdx.y;
    __shared__ float cts[256];
    __shared__ float gs[512];
    int t = threadIdx.x;
    cts[t]      = d_ct[(b*S + t)*H + h];
    gs[t]       = d_g[h*512 + t];
    gs[t + 256] = d_g[h*512 + 256 + t];
    __syncthreads();

    int i  = t + 1;                  // center position, 1..256 (255,256 inactive)
    int ie = min(i, 254);
    float mL = cts[0]   + d_gB0[h*S + ie];    // j=0 is always left (i>=1)
    float mR = cts[255] + d_gB255[h*S + ie];  // j=255 is always right (i<=254)
    const float* gp = gs + 256 - i;
    #pragma unroll 4
    for (int j = 1; j <= 254; ++j) {
        float val = cts[j] + gp[j];
        if (j < i) mL = fmaxf(mL, val);
        else       mR = fmaxf(mR, val);
    }
    if (i <= 254) {
        d_pool[(b*S + i)*(2*H) + h]     = fmaxf(mL, 0.0f);
        d_pool[(b*S + i)*(2*H) + H + h] = fmaxf(mR, 0.0f);
    }
}

// ---------------- final logits ----------------
__global__ void final_kernel(const float* fc_b, float* out) {
    int t = blockIdx.x * blockDim.x + threadIdx.x;
    int l = t & 63;
    int s = (t >> 6) & (S-1);
    int b = t >> 14;
    if (l >= L) return;
    float* o = out + (b*S + s)*L + l;
    if (s == 0 || s == S-1) { *o = (l == L-1) ? 1.0f : 0.0f; return; }
    float acc = fc_b[l];
    const float* pr = d_pool + (b*S + s)*(2*H);
    #pragma unroll 4
    for (int c = 0; c < 2*H; ++c)
        acc += pr[c] * d_fcW2[c*L + l];
    int row = b*S + s;
    acc += d_Y[(row-1)*NP + 600 + l]
         + d_Y[row*NP     + 600 + L + l]
         + d_Y[(row+1)*NP + 600 + 2*L + l];
    *o = acc;
}

extern "C" void kernel_launch(void* const* d_in, const int* in_sizes, int n_in,
                              void* d_out, int out_size) {
    const int*   inputs   = (const int*)d_in[0];   // int32 or int64, detected
    const float* word_emb = (const float*)d_in[1];
    const float* pf_emb   = (const float*)d_in[2];
    const float* conv_W   = (const float*)d_in[3];
    const float* conv_b   = (const float*)d_in[4];
    const float* fc_W     = (const float*)d_in[5];
    const float* fc_b     = (const float*)d_in[6];
    float* out = (float*)d_out;

    detect_kernel<<<1, 256>>>(inputs);
    gather_kernel<<<M, 128>>>(inputs, word_emb);
    pack_wall_kernel<<<KP, 256>>>(conv_W, fc_W);
    pack_fcw2_kernel<<<2*H, 64>>>(fc_W);
    gtables_kernel<<<H, 256>>>(conv_W, pf_emb);

    dim3 ggrid(M/128, NP/64);
    gemm_kernel<<<ggrid, 256>>>();

    ct_kernel<<<M, 256>>>(conv_b);

    dim3 pgrid(H, B);
    pool_kernel<<<pgrid, 256>>>();

    final_kernel<<<(B*S*64)/128, 128>>>(fc_b, out);
}

// round 2
// speedup vs baseline: 1.0109x; 1.0109x over previous
#include <cuda_runtime.h>
#include <cuda_bf16.h>

#define E   300
#define P   5
#define H   200
#define S   256
#define L   34
#define B   8
#define KP  320          // K padded (300 -> 320, 10 chunks of 32)
#define NP  704          // N padded (702 -> 704)
#define M   (B*S)        // 2048
#define FCK (3*E + 2*H)  // 1300

// ---------------- scratch ----------------
__device__ __align__(16) float d_A[M*KP];
__device__ __align__(16) float d_Wall[KP*NP];
__device__ __align__(16) float d_Y[M*NP];
__device__ __align__(16) float d_ct[M*H];
__device__ __align__(16) float d_g[H*512];
__device__ __align__(16) float d_gB0[H*S];
__device__ __align__(16) float d_gB255[H*S];
__device__ __align__(16) float d_pool[M*2*H];
__device__ __align__(16) float d_fcW2[2*H*L];
__device__ int d_is64;

// ---------------- int width detect ----------------
__global__ void detect_kernel(const int* in32) {
    __shared__ int any;
    if (threadIdx.x == 0) any = 0;
    __syncthreads();
    int local = 0;
    for (int t = threadIdx.x; t < 1024; t += blockDim.x)
        if (in32[2*t + 1] != 0) local = 1;
    if (local) atomicOr(&any, 1);
    __syncthreads();
    if (threadIdx.x == 0) d_is64 = (any == 0) ? 1 : 0;
}

// ---------------- fused prep: gather + packs + g-tables ----------------
__global__ void prep_kernel(const int* in32, const float* word_emb,
                            const float* conv_W, const float* fc_W,
                            const float* pf_emb) {
    int blk = blockIdx.x;
    int tid = threadIdx.x;
    if (blk < 2048) {                              // gather token embeddings
        int row = blk;
        long long tok = d_is64 ? ((const long long*)in32)[row]
                               : (long long)in32[row];
        const float* src = word_emb + tok * E;
        for (int e = tid; e < KP; e += 256)
            d_A[row*KP + e] = (e < E) ? src[e] : 0.0f;
    } else if (blk < 2368) {                       // pack Wall
        int e = blk - 2048;                        // 0..319
        for (int c = tid; c < NP; c += 256) {
            float v = 0.0f;
            if (e < E) {
                if (c < 600) {
                    int k = c / 200, h = c % 200;
                    v = conv_W[h*((E+P)*3) + e*3 + k];
                } else if (c < 702) {
                    int cc = c - 600, k = cc / L, l = cc % L;
                    v = fc_W[l*FCK + 2*H + k*E + e];
                }
            }
            d_Wall[e*NP + c] = v;
        }
    } else if (blk == 2368) {                      // pack fcW2[c][l]
        for (int idx = tid; idx < 2*H*L; idx += 256) {
            int c = idx / L, l = idx % L;
            d_fcW2[idx] = fc_W[l*FCK + c];
        }
    } else {                                       // g-tables
        int h = blk - 2369;                        // 0..199
        float w0[P], w1[P], w2[P];
        #pragma unroll
        for (int p = 0; p < P; p++) {
            const float* wp = conv_W + h*(E+P)*3 + (E+p)*3;
            w0[p] = wp[0]; w1[p] = wp[1]; w2[p] = wp[2];
        }
        for (int dd = tid; dd < 512; dd += 256) {
            int d = dd - 256;
            int i0 = abs(d-1); if (i0 > 255) i0 = 255;
            int i1 = abs(d);   if (i1 > 255) i1 = 255;
            int i2 = abs(d+1); if (i2 > 255) i2 = 255;
            float acc = 0.0f;
            #pragma unroll
            for (int p = 0; p < P; p++)
                acc += w0[p]*pf_emb[i0*P+p] + w1[p]*pf_emb[i1*P+p] + w2[p]*pf_emb[i2*P+p];
            d_g[h*512 + dd] = acc;
        }
        if (tid >= 1 && tid <= 254) {
            int i = tid;
            float a0 = 0.0f, a255 = 0.0f;
            #pragma unroll
            for (int p = 0; p < P; p++) {
                a0   += w1[p]*pf_emb[i*P+p] + w2[p]*pf_emb[(i-1)*P+p];
                a255 += w0[p]*pf_emb[(254-i >= 0 ? 254-i : i-254)*P+p] + w1[p]*pf_emb[(255-i)*P+p];
            }
            d_gB0[h*S + i]   = a0;
            d_gB255[h*S + i] = a255;
        }
    }
}

// ---------------- bf16 split tensor-core GEMM ----------------
__device__ __forceinline__ unsigned pk2(float a, float b) {
    __nv_bfloat162 t = __floats2bfloat162_rn(a, b);
    return *reinterpret_cast<unsigned*>(&t);
}
__device__ __forceinline__ float bhi(float x) {
    return __bfloat162float(__float2bfloat16(x));
}
__device__ __forceinline__ void mma_bf16(float* d, const unsigned* a, const unsigned* b) {
    asm volatile("mma.sync.aligned.m16n8k16.row.col.f32.bf16.bf16.f32 "
        "{%0,%1,%2,%3},{%4,%5,%6,%7},{%8,%9},{%0,%1,%2,%3};\n"
        : "+f"(d[0]), "+f"(d[1]), "+f"(d[2]), "+f"(d[3])
        : "r"(a[0]), "r"(a[1]), "r"(a[2]), "r"(a[3]), "r"(b[0]), "r"(b[1]));
}

// Y[2048x704] = A[2048x320] * Wall[320x704], block tile 128x64, 8 warps (4m x 2n),
// warp tile 32x32. bf16 hi/lo split, 3 mma passes, fp32 accumulate.
__global__ __launch_bounds__(256, 2) void gemm_kernel() {
    __shared__ unsigned Ah[128][20], Al[128][20];   // [m][kpair], stride 20: conflict-free frags
    __shared__ unsigned Bh[16][72],  Bl[16][72];    // [kpair][n], stride 72: conflict-free

    const int t = threadIdx.x, lane = t & 31, warp = t >> 5;
    const int wm = warp >> 1, wn = warp & 1;
    const int mBase = wm * 32, nBase = wn * 32;
    const int r0 = lane >> 2, c0 = lane & 3;

    float acc[2][4][4];
    #pragma unroll
    for (int mi = 0; mi < 2; mi++)
        #pragma unroll
        for (int ni = 0; ni < 4; ni++)
            #pragma unroll
            for (int q = 0; q < 4; q++) acc[mi][ni][q] = 0.0f;

    const float* Ag = d_A + (size_t)blockIdx.x * 128 * KP;
    const float* Bg = d_Wall + blockIdx.y * 64;

    const int am  = t >> 1;            // A row 0..127
    const int akq = (t & 1) * 16;      // A float-col base within chunk
    const int bn  = t & 63;            // B col
    const int bkp0 = t >> 6;           // B kpair base

    float4 av[4];
    float bg0[4], bg1[4];
    #pragma unroll
    for (int q = 0; q < 4; q++)
        av[q] = *(const float4*)(Ag + am*KP + akq + q*4);
    #pragma unroll
    for (int it = 0; it < 4; it++) {
        int kp = bkp0 + it*4;
        bg0[it] = Bg[(2*kp)*NP + bn];
        bg1[it] = Bg[(2*kp+1)*NP + bn];
    }

    for (int ch = 0; ch < 10; ch++) {
        __syncthreads();
        // store split chunk into smem
        #pragma unroll
        for (int q = 0; q < 4; q++) {
            float x0 = av[q].x, x1 = av[q].y, x2 = av[q].z, x3 = av[q].w;
            float h0 = bhi(x0), h1 = bhi(x1), h2 = bhi(x2), h3 = bhi(x3);
            int p = (t & 1)*8 + q*2;
            Ah[am][p]   = pk2(h0, h1);
            Ah[am][p+1] = pk2(h2, h3);
            Al[am][p]   = pk2(x0-h0, x1-h1);
            Al[am][p+1] = pk2(x2-h2, x3-h3);
        }
        #pragma unroll
        for (int it = 0; it < 4; it++) {
            int kp = bkp0 + it*4;
            float h0 = bhi(bg0[it]), h1 = bhi(bg1[it]);
            Bh[kp][bn] = pk2(h0, h1);
            Bl[kp][bn] = pk2(bg0[it]-h0, bg1[it]-h1);
        }
        __syncthreads();
        // prefetch next chunk (hides latency behind mma work)
        if (ch < 9) {
            int kc = (ch + 1) * 32;
            #pragma unroll
            for (int q = 0; q < 4; q++)
                av[q] = *(const float4*)(Ag + am*KP + kc + akq + q*4);
            #pragma unroll
            for (int it = 0; it < 4; it++) {
                int kp = bkp0 + it*4;
                bg0[it] = Bg[(kc + 2*kp)*NP + bn];
                bg1[it] = Bg[(kc + 2*kp + 1)*NP + bn];
            }
        }
        // compute: 2 k-steps of 16
        #pragma unroll
        for (int ks = 0; ks < 2; ks++) {
            int p0 = ks*8 + c0;
            unsigned ah[2][4], al[2][4];
            #pragma unroll
            for (int mi = 0; mi < 2; mi++) {
                int mr = mBase + mi*16 + r0;
                ah[mi][0] = Ah[mr][p0];     al[mi][0] = Al[mr][p0];
                ah[mi][1] = Ah[mr+8][p0];   al[mi][1] = Al[mr+8][p0];
                ah[mi][2] = Ah[mr][p0+4];   al[mi][2] = Al[mr][p0+4];
                ah[mi][3] = Ah[mr+8][p0+4]; al[mi][3] = Al[mr+8][p0+4];
            }
            unsigned bh[4][2], bl[4][2];
            #pragma unroll
            for (int ni = 0; ni < 4; ni++) {
                int n = nBase + ni*8 + r0;
                bh[ni][0] = Bh[p0][n];   bl[ni][0] = Bl[p0][n];
                bh[ni][1] = Bh[p0+4][n]; bl[ni][1] = Bl[p0+4][n];
            }
            #pragma unroll
            for (int mi = 0; mi < 2; mi++)
                #pragma unroll
                for (int ni = 0; ni < 4; ni++) {
                    mma_bf16(acc[mi][ni], ah[mi], bh[ni]);
                    mma_bf16(acc[mi][ni], al[mi], bh[ni]);
                    mma_bf16(acc[mi][ni], ah[mi], bl[ni]);
                }
        }
    }
    float* Yg = d_Y + (size_t)(blockIdx.x*128)*NP + blockIdx.y*64;
    #pragma unroll
    for (int mi = 0; mi < 2; mi++) {
        int mr = mBase + mi*16 + r0;
        #pragma unroll
        for (int ni = 0; ni < 4; ni++) {
            int nc = nBase + ni*8 + 2*c0;
            *(float2*)(Yg + mr*NP + nc)     = make_float2(acc[mi][ni][0], acc[mi][ni][1]);
            *(float2*)(Yg + (mr+8)*NP + nc) = make_float2(acc[mi][ni][2], acc[mi][ni][3]);
        }
    }
}

// ---------------- assemble conv_tok ----------------
__global__ void ct_kernel(const float* conv_b) {
    int row = blockIdx.x;
    int j = row & (S-1);
    int h = threadIdx.x;
    if (h >= H) return;
    float v = conv_b[h] + d_Y[row*NP + 200 + h];
    if (j > 0)   v += d_Y[(row-1)*NP + h];
    if (j < S-1) v += d_Y[(row+1)*NP + 400 + h];
    d_ct[row*H + h] = v;
}

// ---------------- max-plus pooling (3-phase warp-uniform split) ----------------
__global__ __launch_bounds__(256) void pool_kernel() {
    int h = blockIdx.x, b = blockIdx.y;
    __shared__ float cts[256];
    __shared__ float gs[512];
    int t = threadIdx.x;
    cts[t]      = d_ct[(b*S + t)*H + h];
    gs[t]       = d_g[h*512 + t];
    gs[t + 256] = d_g[h*512 + 256 + t];
    __syncthreads();

    int i  = t + 1;
    int ie = min(i, 254);
    float mL = cts[0]   + d_gB0[h*S + ie];
    float mR = cts[255] + d_gB255[h*S + ie];
    const float* gp = gs + 256 - i;
    int i0 = (t & ~31) + 1;                  // warp-min center
    // all-left region: j in [1, i0)  (j < i for every lane)
    #pragma unroll 4
    for (int j = 1; j < i0; ++j) mL = fmaxf(mL, cts[j] + gp[j]);
    // mixed region: j in [i0, i0+30]
    int jm = min(i0 + 30, 254);
    for (int j = i0; j <= jm; ++j) {
        float v = cts[j] + gp[j];
        if (j < i) mL = fmaxf(mL, v); else mR = fmaxf(mR, v);
    }
    // all-right region: j in [i0+31, 254]
    #pragma unroll 4
    for (int j = i0 + 31; j <= 254; ++j) mR = fmaxf(mR, cts[j] + gp[j]);

    if (i <= 254) {
        d_pool[(b*S + i)*(2*H) + h]     = fmaxf(mL, 0.0f);
        d_pool[(b*S + i)*(2*H) + H + h] = fmaxf(mR, 0.0f);
    }
}

// ---------------- final logits: warp per (b,s) ----------------
__global__ __launch_bounds__(256) void final_kernel(const float* fc_b, float* out) {
    int gw = (blockIdx.x * 256 + threadIdx.x) >> 5;   // 0..2047 = b*256+s
    int lane = threadIdx.x & 31;
    int s = gw & (S-1);
    float* o = out + gw * L;
    if (s == 0 || s == S-1) {
        o[lane] = 0.0f;                                // l = 0..31
        if (lane < 2) o[lane + 32] = (lane == 1) ? 1.0f : 0.0f;
        return;
    }
    float acc0 = fc_b[lane];
    float acc1 = (lane < 2) ? fc_b[lane + 32] : 0.0f;
    const float* pr = d_pool + gw * (2*H);
    #pragma unroll 4
    for (int c = 0; c < 2*H; ++c) {
        float p = pr[c];
        acc0 += p * d_fcW2[c*L + lane];
        if (lane < 2) acc1 += p * d_fcW2[c*L + lane + 32];
    }
    acc0 += d_Y[(gw-1)*NP + 600 + lane]
          + d_Y[gw*NP     + 634 + lane]
          + d_Y[(gw+1)*NP + 668 + lane];
    o[lane] = acc0;
    if (lane < 2) {
        acc1 += d_Y[(gw-1)*NP + 632 + lane]
              + d_Y[gw*NP     + 666 + lane]
              + d_Y[(gw+1)*NP + 700 + lane];
        o[lane + 32] = acc1;
    }
}

extern "C" void kernel_launch(void* const* d_in, const int* in_sizes, int n_in,
                              void* d_out, int out_size) {
    const int*   inputs   = (const int*)d_in[0];
    const float* word_emb = (const float*)d_in[1];
    const float* pf_emb   = (const float*)d_in[2];
    const float* conv_W   = (const float*)d_in[3];
    const float* conv_b   = (const float*)d_in[4];
    const float* fc_W     = (const float*)d_in[5];
    const float* fc_b     = (const float*)d_in[6];
    float* out = (float*)d_out;

    detect_kernel<<<1, 256>>>(inputs);
    prep_kernel<<<2569, 256>>>(inputs, word_emb, conv_W, fc_W, pf_emb);

    dim3 ggrid(M/128, NP/64);
    gemm_kernel<<<ggrid, 256>>>();

    ct_kernel<<<M, 256>>>(conv_b);

    dim3 pgrid(H, B);
    pool_kernel<<<pgrid, 256>>>();

    final_kernel<<<256, 256>>>(fc_b, out);
}

// round 3
// speedup vs baseline: 1.2771x; 1.2633x over previous
#include <cuda_runtime.h>
#include <cuda_bf16.h>

#define E   300
#define P   5
#define H   200
#define S   256
#define L   34
#define B   8
#define KP  320          // K padded (300 -> 320, 10 chunks of 32)
#define NP  704          // N padded (702 -> 704)
#define M   (B*S)        // 2048
#define FCK (3*E + 2*H)  // 1300

// ---------------- scratch ----------------
__device__ __align__(16) float d_A[M*KP];
__device__ __align__(16) float d_Wall[KP*NP];
__device__ __align__(16) float d_Y[M*NP];
__device__ __align__(16) float d_ct[M*H];
__device__ __align__(16) float d_g[512*H];        // [d][h]
__device__ __align__(16) float d_gB0[S*H];        // [i][h]
__device__ __align__(16) float d_gB255[S*H];      // [i][h]
__device__ __align__(16) float d_pool[M*2*H];
__device__ __align__(16) float d_fcW2t[L*400];    // [l][c]
__device__ int d_is64;

// ---------------- int width detect ----------------
__global__ void detect_kernel(const int* in32) {
    __shared__ int any;
    if (threadIdx.x == 0) any = 0;
    __syncthreads();
    int local = 0;
    for (int t = threadIdx.x; t < 1024; t += blockDim.x)
        if (in32[2*t + 1] != 0) local = 1;
    if (local) atomicOr(&any, 1);
    __syncthreads();
    if (threadIdx.x == 0) d_is64 = (any == 0) ? 1 : 0;
}

// ---------------- fused prep ----------------
__global__ void prep_kernel(const int* in32, const float* word_emb,
                            const float* conv_W, const float* fc_W,
                            const float* pf_emb) {
    int blk = blockIdx.x;
    int tid = threadIdx.x;
    if (blk < 2048) {                              // gather token embeddings
        int row = blk;
        long long tok = d_is64 ? ((const long long*)in32)[row]
                               : (long long)in32[row];
        const float* src = word_emb + tok * E;
        for (int e = tid; e < KP; e += 256)
            d_A[row*KP + e] = (e < E) ? src[e] : 0.0f;
    } else if (blk < 2368) {                       // pack Wall
        int e = blk - 2048;                        // 0..319
        for (int c = tid; c < NP; c += 256) {
            float v = 0.0f;
            if (e < E) {
                if (c < 600) {
                    int k = c / 200, h = c % 200;
                    v = conv_W[h*((E+P)*3) + e*3 + k];
                } else if (c < 702) {
                    int cc = c - 600, k = cc / L, l = cc % L;
                    v = fc_W[l*FCK + 2*H + k*E + e];
                }
            }
            d_Wall[e*NP + c] = v;
        }
    } else if (blk == 2368) {                      // pack fcW2t[l][c]
        for (int idx = tid; idx < L*400; idx += 256) {
            int l = idx / 400, c = idx % 400;
            d_fcW2t[idx] = fc_W[l*FCK + c];
        }
    } else {                                       // g-tables (transposed [d][h])
        int h = blk - 2369;                        // 0..199
        float w0[P], w1[P], w2[P];
        #pragma unroll
        for (int p = 0; p < P; p++) {
            const float* wp = conv_W + h*(E+P)*3 + (E+p)*3;
            w0[p] = wp[0]; w1[p] = wp[1]; w2[p] = wp[2];
        }
        for (int dd = tid; dd < 512; dd += 256) {
            int d = dd - 256;
            int i0 = abs(d-1); if (i0 > 255) i0 = 255;
            int i1 = abs(d);   if (i1 > 255) i1 = 255;
            int i2 = abs(d+1); if (i2 > 255) i2 = 255;
            float acc = 0.0f;
            #pragma unroll
            for (int p = 0; p < P; p++)
                acc += w0[p]*pf_emb[i0*P+p] + w1[p]*pf_emb[i1*P+p] + w2[p]*pf_emb[i2*P+p];
            d_g[dd*H + h] = acc;
        }
        if (tid >= 1 && tid <= 254) {
            int i = tid;
            float a0 = 0.0f, a255 = 0.0f;
            #pragma unroll
            for (int p = 0; p < P; p++) {
                a0   += w1[p]*pf_emb[i*P+p] + w2[p]*pf_emb[(i-1)*P+p];
                a255 += w0[p]*pf_emb[(254-i >= 0 ? 254-i : i-254)*P+p] + w1[p]*pf_emb[(255-i)*P+p];
            }
            d_gB0[i*H + h]   = a0;
            d_gB255[i*H + h] = a255;
        }
    }
}

// ---------------- bf16 split tensor-core GEMM ----------------
__device__ __forceinline__ unsigned pk2(float a, float b) {
    __nv_bfloat162 t = __floats2bfloat162_rn(a, b);
    return *reinterpret_cast<unsigned*>(&t);
}
__device__ __forceinline__ float bhi(float x) {
    return __bfloat162float(__float2bfloat16(x));
}
__device__ __forceinline__ void mma_bf16(float* d, const unsigned* a, const unsigned* b) {
    asm volatile("mma.sync.aligned.m16n8k16.row.col.f32.bf16.bf16.f32 "
        "{%0,%1,%2,%3},{%4,%5,%6,%7},{%8,%9},{%0,%1,%2,%3};\n"
        : "+f"(d[0]), "+f"(d[1]), "+f"(d[2]), "+f"(d[3])
        : "r"(a[0]), "r"(a[1]), "r"(a[2]), "r"(a[3]), "r"(b[0]), "r"(b[1]));
}

__global__ __launch_bounds__(256, 2) void gemm_kernel() {
    __shared__ unsigned Ah[128][20], Al[128][20];
    __shared__ unsigned Bh[16][72],  Bl[16][72];

    const int t = threadIdx.x, lane = t & 31, warp = t >> 5;
    const int wm = warp >> 1, wn = warp & 1;
    const int mBase = wm * 32, nBase = wn * 32;
    const int r0 = lane >> 2, c0 = lane & 3;

    float acc[2][4][4];
    #pragma unroll
    for (int mi = 0; mi < 2; mi++)
        #pragma unroll
        for (int ni = 0; ni < 4; ni++)
            #pragma unroll
            for (int q = 0; q < 4; q++) acc[mi][ni][q] = 0.0f;

    const float* Ag = d_A + (size_t)blockIdx.x * 128 * KP;
    const float* Bg = d_Wall + blockIdx.y * 64;

    const int am  = t >> 1;
    const int akq = (t & 1) * 16;
    const int bn  = t & 63;
    const int bkp0 = t >> 6;

    float4 av[4];
    float bg0[4], bg1[4];
    #pragma unroll
    for (int q = 0; q < 4; q++)
        av[q] = *(const float4*)(Ag + am*KP + akq + q*4);
    #pragma unroll
    for (int it = 0; it < 4; it++) {
        int kp = bkp0 + it*4;
        bg0[it] = Bg[(2*kp)*NP + bn];
        bg1[it] = Bg[(2*kp+1)*NP + bn];
    }

    for (int ch = 0; ch < 10; ch++) {
        __syncthreads();
        #pragma unroll
        for (int q = 0; q < 4; q++) {
            float x0 = av[q].x, x1 = av[q].y, x2 = av[q].z, x3 = av[q].w;
            float h0 = bhi(x0), h1 = bhi(x1), h2 = bhi(x2), h3 = bhi(x3);
            int p = (t & 1)*8 + q*2;
            Ah[am][p]   = pk2(h0, h1);
            Ah[am][p+1] = pk2(h2, h3);
            Al[am][p]   = pk2(x0-h0, x1-h1);
            Al[am][p+1] = pk2(x2-h2, x3-h3);
        }
        #pragma unroll
        for (int it = 0; it < 4; it++) {
            int kp = bkp0 + it*4;
            float h0 = bhi(bg0[it]), h1 = bhi(bg1[it]);
            Bh[kp][bn] = pk2(h0, h1);
            Bl[kp][bn] = pk2(bg0[it]-h0, bg1[it]-h1);
        }
        __syncthreads();
        if (ch < 9) {
            int kc = (ch + 1) * 32;
            #pragma unroll
            for (int q = 0; q < 4; q++)
                av[q] = *(const float4*)(Ag + am*KP + kc + akq + q*4);
            #pragma unroll
            for (int it = 0; it < 4; it++) {
                int kp = bkp0 + it*4;
                bg0[it] = Bg[(kc + 2*kp)*NP + bn];
                bg1[it] = Bg[(kc + 2*kp + 1)*NP + bn];
            }
        }
        #pragma unroll
        for (int ks = 0; ks < 2; ks++) {
            int p0 = ks*8 + c0;
            unsigned ah[2][4], al[2][4];
            #pragma unroll
            for (int mi = 0; mi < 2; mi++) {
                int mr = mBase + mi*16 + r0;
                ah[mi][0] = Ah[mr][p0];     al[mi][0] = Al[mr][p0];
                ah[mi][1] = Ah[mr+8][p0];   al[mi][1] = Al[mr+8][p0];
                ah[mi][2] = Ah[mr][p0+4];   al[mi][2] = Al[mr][p0+4];
                ah[mi][3] = Ah[mr+8][p0+4]; al[mi][3] = Al[mr+8][p0+4];
            }
            unsigned bh[4][2], bl[4][2];
            #pragma unroll
            for (int ni = 0; ni < 4; ni++) {
                int n = nBase + ni*8 + r0;
                bh[ni][0] = Bh[p0][n];   bl[ni][0] = Bl[p0][n];
                bh[ni][1] = Bh[p0+4][n]; bl[ni][1] = Bl[p0+4][n];
            }
            #pragma unroll
            for (int mi = 0; mi < 2; mi++)
                #pragma unroll
                for (int ni = 0; ni < 4; ni++) {
                    mma_bf16(acc[mi][ni], ah[mi], bh[ni]);
                    mma_bf16(acc[mi][ni], al[mi], bh[ni]);
                    mma_bf16(acc[mi][ni], ah[mi], bl[ni]);
                }
        }
    }
    float* Yg = d_Y + (size_t)(blockIdx.x*128)*NP + blockIdx.y*64;
    #pragma unroll
    for (int mi = 0; mi < 2; mi++) {
        int mr = mBase + mi*16 + r0;
        #pragma unroll
        for (int ni = 0; ni < 4; ni++) {
            int nc = nBase + ni*8 + 2*c0;
            *(float2*)(Yg + mr*NP + nc)     = make_float2(acc[mi][ni][0], acc[mi][ni][1]);
            *(float2*)(Yg + (mr+8)*NP + nc) = make_float2(acc[mi][ni][2], acc[mi][ni][3]);
        }
    }
}

// ---------------- assemble conv_tok (float4 per thread) ----------------
__global__ __launch_bounds__(256) void ct_kernel(const float* conv_b) {
    int tg  = blockIdx.x * 256 + threadIdx.x;   // 0..102399
    int row = tg / 50;
    int h4  = (tg - row * 50) * 4;
    int j = row & (S-1);
    float4 v  = *(const float4*)(conv_b + h4);
    float4 y1 = *(const float4*)(d_Y + row*NP + 200 + h4);
    v.x += y1.x; v.y += y1.y; v.z += y1.z; v.w += y1.w;
    if (j > 0) {
        float4 y0 = *(const float4*)(d_Y + (row-1)*NP + h4);
        v.x += y0.x; v.y += y0.y; v.z += y0.z; v.w += y0.w;
    }
    if (j < S-1) {
        float4 y2 = *(const float4*)(d_Y + (row+1)*NP + 400 + h4);
        v.x += y2.x; v.y += y2.y; v.z += y2.z; v.w += y2.w;
    }
    *(float4*)(d_ct + row*H + h4) = v;
}

// ---------------- max-plus pooling: 2 centers x 2 channels per thread ----------------
__device__ __forceinline__ float2 add2(float2 a, float2 b) {
    return make_float2(a.x + b.x, a.y + b.y);
}
__device__ __forceinline__ float2 max2(float2 a, float2 b) {
    return make_float2(fmaxf(a.x, b.x), fmaxf(a.y, b.y));
}

__global__ __launch_bounds__(128) void pool_kernel() {
    int hp = blockIdx.x;            // h-pair 0..99
    int b  = blockIdx.y;
    __shared__ float2 cts[256];
    __shared__ float2 gs_e[256];    // g[2q][h-pair]
    __shared__ float2 gs_o[256];    // g[2q+1][h-pair]
    int t = threadIdx.x;            // 0..127

    cts[t]     = *(const float2*)&d_ct[(b*S + t)*H + 2*hp];
    cts[t+128] = *(const float2*)&d_ct[(b*S + t + 128)*H + 2*hp];
    #pragma unroll
    for (int q = 0; q < 2; q++) {
        int e = t + q*128;
        gs_e[e] = *(const float2*)&d_g[(2*e)*H + 2*hp];
        gs_o[e] = *(const float2*)&d_g[(2*e + 1)*H + 2*hp];
    }
    __syncthreads();

    int i0 = 2*t + 1, i1 = 2*t + 2;         // centers (i0 odd)
    int ie0 = min(i0, 254), ie1 = min(i1, 254);

    float2 c0v = cts[0], c255 = cts[255];
    float2 mL0 = add2(c0v, *(const float2*)&d_gB0[ie0*H + 2*hp]);
    float2 mL1 = add2(c0v, *(const float2*)&d_gB0[ie1*H + 2*hp]);
    float2 mR0 = add2(c255, *(const float2*)&d_gB255[ie0*H + 2*hp]);
    float2 mR1 = add2(c255, *(const float2*)&d_gB255[ie1*H + 2*hp]);

    // dd(j, i0) = j - i0 + 256 = j + 255 - 2t : parity flips per j; rotation g_prev
    float2 gprev = gs_o[127 - t];           // ga at j=0
    int idx = 128 - t;                      // gs_e index for j=1
    int w = t >> 5;
    int jA = 64*w;                          // all-left:  j in [1, jA]
    int jB = min(64*w + 64, 254);           // mixed:     j in (jA, jB]
    int j = 1;

    // phase 1: all-left (both centers)
    #pragma unroll 2
    for (; j + 1 <= jA; j += 2) {
        float2 c1 = cts[j],   ga = gs_e[idx];
        mL0 = max2(mL0, add2(c1, ga));
        mL1 = max2(mL1, add2(c1, gprev));
        float2 c2 = cts[j+1], gb = gs_o[idx];
        mL0 = max2(mL0, add2(c2, gb));
        mL1 = max2(mL1, add2(c2, ga));
        gprev = gb; idx++;
    }
    // phase 2: mixed
    for (; j + 1 <= jB; j += 2) {
        float2 c1 = cts[j],   ga = gs_e[idx];
        float2 v0 = add2(c1, ga), v1 = add2(c1, gprev);
        if (j < i0) mL0 = max2(mL0, v0); else mR0 = max2(mR0, v0);
        if (j < i1) mL1 = max2(mL1, v1); else mR1 = max2(mR1, v1);
        float2 c2 = cts[j+1], gb = gs_o[idx];
        float2 u0 = add2(c2, gb), u1 = add2(c2, ga);
        if (j+1 < i0) mL0 = max2(mL0, u0); else mR0 = max2(mR0, u0);
        if (j+1 < i1) mL1 = max2(mL1, u1); else mR1 = max2(mR1, u1);
        gprev = gb; idx++;
    }
    // phase 3: all-right
    #pragma unroll 2
    for (; j + 1 <= 254; j += 2) {
        float2 c1 = cts[j],   ga = gs_e[idx];
        mR0 = max2(mR0, add2(c1, ga));
        mR1 = max2(mR1, add2(c1, gprev));
        float2 c2 = cts[j+1], gb = gs_o[idx];
        mR0 = max2(mR0, add2(c2, gb));
        mR1 = max2(mR1, add2(c2, ga));
        gprev = gb; idx++;
    }

    float2 z = make_float2(0.0f, 0.0f);
    if (t < 127) {  // i0 <= 253, i1 <= 254
        float* p0 = d_pool + (b*S + i0)*(2*H) + 2*hp;
        *(float2*)(p0)     = max2(mL0, z);
        *(float2*)(p0 + H) = max2(mR0, z);
        float* p1 = d_pool + (b*S + i1)*(2*H) + 2*hp;
        *(float2*)(p1)     = max2(mL1, z);
        *(float2*)(p1 + H) = max2(mR1, z);
    }
}

// ---------------- final logits: warp per (b,s), transposed W ----------------
__global__ __launch_bounds__(256) void final_kernel(const float* fc_b, float* out) {
    int gw = (blockIdx.x * 256 + threadIdx.x) >> 5;   // 0..2047 = b*256+s
    int lane = threadIdx.x & 31;
    int s = gw & (S-1);
    float* o = out + gw * L;
    if (s == 0 || s == S-1) {
        o[lane] = 0.0f;
        if (lane < 2) o[lane + 32] = (lane == 1) ? 1.0f : 0.0f;
        return;
    }
    const float* pr = d_pool + gw * (2*H);
    const float* Wl = d_fcW2t + lane * 400;
    float a0 = 0.f, a1 = 0.f, a2 = 0.f, a3 = 0.f;
    #pragma unroll 4
    for (int c = 0; c < 400; c += 4) {
        float4 p = *(const float4*)(pr + c);     // warp-uniform broadcast
        float4 wv = *(const float4*)(Wl + c);
        a0 += p.x * wv.x; a1 += p.y * wv.y;
        a2 += p.z * wv.z; a3 += p.w * wv.w;
    }
    float acc0 = (a0 + a1) + (a2 + a3) + fc_b[lane];
    acc0 += d_Y[(gw-1)*NP + 600 + lane]
          + d_Y[gw*NP     + 634 + lane]
          + d_Y[(gw+1)*NP + 668 + lane];
    o[lane] = acc0;

    // l = 32, 33 via k-strided partials + warp reduction
    const float* W32 = d_fcW2t + 32 * 400;
    const float* W33 = d_fcW2t + 33 * 400;
    float r32 = 0.f, r33 = 0.f;
    #pragma unroll
    for (int c = lane; c < 400; c += 32) {
        float p = pr[c];
        r32 += p * W32[c];
        r33 += p * W33[c];
    }
    #pragma unroll
    for (int off = 16; off > 0; off >>= 1) {
        r32 += __shfl_xor_sync(0xFFFFFFFF, r32, off);
        r33 += __shfl_xor_sync(0xFFFFFFFF, r33, off);
    }
    if (lane < 2) {
        float r = (lane == 0) ? r32 : r33;
        r += fc_b[32 + lane]
           + d_Y[(gw-1)*NP + 632 + lane]
           + d_Y[gw*NP     + 666 + lane]
           + d_Y[(gw+1)*NP + 700 + lane];
        o[32 + lane] = r;
    }
}

extern "C" void kernel_launch(void* const* d_in, const int* in_sizes, int n_in,
                              void* d_out, int out_size) {
    const int*   inputs   = (const int*)d_in[0];
    const float* word_emb = (const float*)d_in[1];
    const float* pf_emb   = (const float*)d_in[2];
    const float* conv_W   = (const float*)d_in[3];
    const float* conv_b   = (const float*)d_in[4];
    const float* fc_W     = (const float*)d_in[5];
    const float* fc_b     = (const float*)d_in[6];
    float* out = (float*)d_out;

    detect_kernel<<<1, 256>>>(inputs);
    prep_kernel<<<2569, 256>>>(inputs, word_emb, conv_W, fc_W, pf_emb);

    dim3 ggrid(M/128, NP/64);
    gemm_kernel<<<ggrid, 256>>>();

    ct_kernel<<<400, 256>>>(conv_b);

    dim3 pgrid(H/2, B);
    pool_kernel<<<pgrid, 128>>>();

    final_kernel<<<256, 256>>>(fc_b, out);
}

// round 4
// speedup vs baseline: 1.3287x; 1.0404x over previous
#include <cuda_runtime.h>
#include <cuda_bf16.h>

#define E   300
#define P   5
#define H   200
#define S   256
#define L   34
#define B   8
#define KP  320          // K padded (300 -> 320, 10 chunks of 32)
#define NP  704          // N padded (702 -> 704)
#define M   (B*S)        // 2048
#define FCK (3*E + 2*H)  // 1300

// ---------------- scratch ----------------
__device__ __align__(16) float d_A[M*KP];
__device__ __align__(16) float d_Wall[KP*NP];
__device__ __align__(16) float d_Y[M*NP];
__device__ __align__(16) float d_g[512*H];        // [d][h]
__device__ __align__(16) float d_gB0[S*H];        // [i][h]
__device__ __align__(16) float d_gB255[S*H];      // [i][h]
__device__ __align__(16) float d_pool[M*2*H];
__device__ __align__(16) float d_fcW2t[L*400];    // [l][c]

// ---------------- packed f32x2 add ----------------
union F2U { float2 f; unsigned long long u; };
__device__ __forceinline__ float2 add2(float2 a, float2 b) {
    F2U ua, ub, uc;
    ua.f = a; ub.f = b;
    asm("add.rn.f32x2 %0, %1, %2;" : "=l"(uc.u) : "l"(ua.u), "l"(ub.u));
    return uc.f;
}
__device__ __forceinline__ float2 max2(float2 a, float2 b) {
    return make_float2(fmaxf(a.x, b.x), fmaxf(a.y, b.y));
}

// ---------------- gather (with inline int-width detection) ----------------
__global__ __launch_bounds__(320) void gather_kernel(const int* in32, const float* word_emb) {
    int row = blockIdx.x;
    int lane = threadIdx.x & 31;
    // int64 inputs have all-zero high words; int32 tokens make this ~impossible
    int hw = in32[2*lane + 1];
    unsigned nz = __ballot_sync(0xffffffffu, hw != 0);
    long long tok = (nz == 0) ? ((const long long*)in32)[row]
                              : (long long)in32[row];
    const float* src = word_emb + tok * E;
    int e = threadIdx.x;                           // 0..319, one element each
    d_A[row*KP + e] = (e < E) ? src[e] : 0.0f;
}

// ---------------- pack: Wall + fcW2t + g-tables ----------------
__global__ void pack_kernel(const float* conv_W, const float* fc_W, const float* pf_emb) {
    int blk = blockIdx.x;
    int tid = threadIdx.x;
    if (blk < 320) {                               // pack Wall
        int e = blk;
        for (int c = tid; c < NP; c += 256) {
            float v = 0.0f;
            if (e < E) {
                if (c < 600) {
                    int k = c / 200, h = c % 200;
                    v = conv_W[h*((E+P)*3) + e*3 + k];
                } else if (c < 702) {
                    int cc = c - 600, k = cc / L, l = cc % L;
                    v = fc_W[l*FCK + 2*H + k*E + e];
                }
            }
            d_Wall[e*NP + c] = v;
        }
    } else if (blk == 320) {                       // pack fcW2t[l][c]
        for (int idx = tid; idx < L*400; idx += 256) {
            int l = idx / 400, c = idx % 400;
            d_fcW2t[idx] = fc_W[l*FCK + c];
        }
    } else {                                       // g-tables (transposed [d][h])
        int h = blk - 321;                         // 0..199
        float w0[P], w1[P], w2[P];
        #pragma unroll
        for (int p = 0; p < P; p++) {
            const float* wp = conv_W + h*(E+P)*3 + (E+p)*3;
            w0[p] = wp[0]; w1[p] = wp[1]; w2[p] = wp[2];
        }
        for (int dd = tid; dd < 512; dd += 256) {
            int d = dd - 256;
            int i0 = abs(d-1); if (i0 > 255) i0 = 255;
            int i1 = abs(d);   if (i1 > 255) i1 = 255;
            int i2 = abs(d+1); if (i2 > 255) i2 = 255;
            float acc = 0.0f;
            #pragma unroll
            for (int p = 0; p < P; p++)
                acc += w0[p]*pf_emb[i0*P+p] + w1[p]*pf_emb[i1*P+p] + w2[p]*pf_emb[i2*P+p];
            d_g[dd*H + h] = acc;
        }
        if (tid >= 1 && tid <= 254) {
            int i = tid;
            float a0 = 0.0f, a255 = 0.0f;
            #pragma unroll
            for (int p = 0; p < P; p++) {
                a0   += w1[p]*pf_emb[i*P+p] + w2[p]*pf_emb[(i-1)*P+p];
                a255 += w0[p]*pf_emb[(254-i >= 0 ? 254-i : i-254)*P+p] + w1[p]*pf_emb[(255-i)*P+p];
            }
            d_gB0[i*H + h]   = a0;
            d_gB255[i*H + h] = a255;
        }
    }
}

// ---------------- bf16 split tensor-core GEMM ----------------
__device__ __forceinline__ unsigned pk2(float a, float b) {
    __nv_bfloat162 t = __floats2bfloat162_rn(a, b);
    return *reinterpret_cast<unsigned*>(&t);
}
__device__ __forceinline__ float bhi(float x) {
    return __bfloat162float(__float2bfloat16(x));
}
__device__ __forceinline__ void mma_bf16(float* d, const unsigned* a, const unsigned* b) {
    asm volatile("mma.sync.aligned.m16n8k16.row.col.f32.bf16.bf16.f32 "
        "{%0,%1,%2,%3},{%4,%5,%6,%7},{%8,%9},{%0,%1,%2,%3};\n"
        : "+f"(d[0]), "+f"(d[1]), "+f"(d[2]), "+f"(d[3])
        : "r"(a[0]), "r"(a[1]), "r"(a[2]), "r"(a[3]), "r"(b[0]), "r"(b[1]));
}

__global__ __launch_bounds__(256, 2) void gemm_kernel() {
    __shared__ unsigned Ah[128][20], Al[128][20];
    __shared__ unsigned Bh[16][72],  Bl[16][72];

    const int t = threadIdx.x, lane = t & 31, warp = t >> 5;
    const int wm = warp >> 1, wn = warp & 1;
    const int mBase = wm * 32, nBase = wn * 32;
    const int r0 = lane >> 2, c0 = lane & 3;

    float acc[2][4][4];
    #pragma unroll
    for (int mi = 0; mi < 2; mi++)
        #pragma unroll
        for (int ni = 0; ni < 4; ni++)
            #pragma unroll
            for (int q = 0; q < 4; q++) acc[mi][ni][q] = 0.0f;

    const float* Ag = d_A + (size_t)blockIdx.x * 128 * KP;
    const float* Bg = d_Wall + blockIdx.y * 64;

    const int am  = t >> 1;
    const int akq = (t & 1) * 16;
    const int bn  = t & 63;
    const int bkp0 = t >> 6;

    float4 av[4];
    float bg0[4], bg1[4];
    #pragma unroll
    for (int q = 0; q < 4; q++)
        av[q] = *(const float4*)(Ag + am*KP + akq + q*4);
    #pragma unroll
    for (int it = 0; it < 4; it++) {
        int kp = bkp0 + it*4;
        bg0[it] = Bg[(2*kp)*NP + bn];
        bg1[it] = Bg[(2*kp+1)*NP + bn];
    }

    for (int ch = 0; ch < 10; ch++) {
        __syncthreads();
        #pragma unroll
        for (int q = 0; q < 4; q++) {
            float x0 = av[q].x, x1 = av[q].y, x2 = av[q].z, x3 = av[q].w;
            float h0 = bhi(x0), h1 = bhi(x1), h2 = bhi(x2), h3 = bhi(x3);
            int p = (t & 1)*8 + q*2;
            Ah[am][p]   = pk2(h0, h1);
            Ah[am][p+1] = pk2(h2, h3);
            Al[am][p]   = pk2(x0-h0, x1-h1);
            Al[am][p+1] = pk2(x2-h2, x3-h3);
        }
        #pragma unroll
        for (int it = 0; it < 4; it++) {
            int kp = bkp0 + it*4;
            float h0 = bhi(bg0[it]), h1 = bhi(bg1[it]);
            Bh[kp][bn] = pk2(h0, h1);
            Bl[kp][bn] = pk2(bg0[it]-h0, bg1[it]-h1);
        }
        __syncthreads();
        if (ch < 9) {
            int kc = (ch + 1) * 32;
            #pragma unroll
            for (int q = 0; q < 4; q++)
                av[q] = *(const float4*)(Ag + am*KP + kc + akq + q*4);
            #pragma unroll
            for (int it = 0; it < 4; it++) {
                int kp = bkp0 + it*4;
                bg0[it] = Bg[(kc + 2*kp)*NP + bn];
                bg1[it] = Bg[(kc + 2*kp + 1)*NP + bn];
            }
        }
        #pragma unroll
        for (int ks = 0; ks < 2; ks++) {
            int p0 = ks*8 + c0;
            unsigned ah[2][4], al[2][4];
            #pragma unroll
            for (int mi = 0; mi < 2; mi++) {
                int mr = mBase + mi*16 + r0;
                ah[mi][0] = Ah[mr][p0];     al[mi][0] = Al[mr][p0];
                ah[mi][1] = Ah[mr+8][p0];   al[mi][1] = Al[mr+8][p0];
                ah[mi][2] = Ah[mr][p0+4];   al[mi][2] = Al[mr][p0+4];
                ah[mi][3] = Ah[mr+8][p0+4]; al[mi][3] = Al[mr+8][p0+4];
            }
            unsigned bh[4][2], bl[4][2];
            #pragma unroll
            for (int ni = 0; ni < 4; ni++) {
                int n = nBase + ni*8 + r0;
                bh[ni][0] = Bh[p0][n];   bl[ni][0] = Bl[p0][n];
                bh[ni][1] = Bh[p0+4][n]; bl[ni][1] = Bl[p0+4][n];
            }
            #pragma unroll
            for (int mi = 0; mi < 2; mi++)
                #pragma unroll
                for (int ni = 0; ni < 4; ni++) {
                    mma_bf16(acc[mi][ni], ah[mi], bh[ni]);
                    mma_bf16(acc[mi][ni], al[mi], bh[ni]);
                    mma_bf16(acc[mi][ni], ah[mi], bl[ni]);
                }
        }
    }
    float* Yg = d_Y + (size_t)(blockIdx.x*128)*NP + blockIdx.y*64;
    #pragma unroll
    for (int mi = 0; mi < 2; mi++) {
        int mr = mBase + mi*16 + r0;
        #pragma unroll
        for (int ni = 0; ni < 4; ni++) {
            int nc = nBase + ni*8 + 2*c0;
            *(float2*)(Yg + mr*NP + nc)     = make_float2(acc[mi][ni][0], acc[mi][ni][1]);
            *(float2*)(Yg + (mr+8)*NP + nc) = make_float2(acc[mi][ni][2], acc[mi][ni][3]);
        }
    }
}

// ---------------- fused ct + max-plus pooling ----------------
__device__ __forceinline__ float2 compute_ct(int b, int j, int hp, float2 cb) {
    int row = b*S + j;
    float2 v = add2(cb, *(const float2*)&d_Y[row*NP + 200 + 2*hp]);
    if (j > 0)   v = add2(v, *(const float2*)&d_Y[(row-1)*NP + 2*hp]);
    if (j < S-1) v = add2(v, *(const float2*)&d_Y[(row+1)*NP + 400 + 2*hp]);
    return v;
}

__global__ __launch_bounds__(128) void pool_kernel(const float* conv_b) {
    int hp = blockIdx.x;            // h-pair 0..99
    int b  = blockIdx.y;
    __shared__ float2 cts[256];
    __shared__ float2 gs_e[256];    // g[2q][h-pair]
    __shared__ float2 gs_o[256];    // g[2q+1][h-pair]
    int t = threadIdx.x;            // 0..127

    float2 cb = *(const float2*)&conv_b[2*hp];
    cts[t]     = compute_ct(b, t, hp, cb);
    cts[t+128] = compute_ct(b, t+128, hp, cb);
    #pragma unroll
    for (int q = 0; q < 2; q++) {
        int e = t + q*128;
        gs_e[e] = *(const float2*)&d_g[(2*e)*H + 2*hp];
        gs_o[e] = *(const float2*)&d_g[(2*e + 1)*H + 2*hp];
    }
    __syncthreads();

    int i0 = 2*t + 1, i1 = 2*t + 2;
    int ie0 = min(i0, 254), ie1 = min(i1, 254);

    float2 c0v = cts[0], c255 = cts[255];
    float2 mL0 = add2(c0v, *(const float2*)&d_gB0[ie0*H + 2*hp]);
    float2 mL1 = add2(c0v, *(const float2*)&d_gB0[ie1*H + 2*hp]);
    float2 mR0 = add2(c255, *(const float2*)&d_gB255[ie0*H + 2*hp]);
    float2 mR1 = add2(c255, *(const float2*)&d_gB255[ie1*H + 2*hp]);

    float2 gprev = gs_o[127 - t];
    int idx = 128 - t;
    int w = t >> 5;
    int jA = 64*w;
    int jB = min(64*w + 64, 254);
    int j = 1;

    #pragma unroll 2
    for (; j + 1 <= jA; j += 2) {
        float2 c1 = cts[j],   ga = gs_e[idx];
        mL0 = max2(mL0, add2(c1, ga));
        mL1 = max2(mL1, add2(c1, gprev));
        float2 c2 = cts[j+1], gb = gs_o[idx];
        mL0 = max2(mL0, add2(c2, gb));
        mL1 = max2(mL1, add2(c2, ga));
        gprev = gb; idx++;
    }
    for (; j + 1 <= jB; j += 2) {
        float2 c1 = cts[j],   ga = gs_e[idx];
        float2 v0 = add2(c1, ga), v1 = add2(c1, gprev);
        if (j < i0) mL0 = max2(mL0, v0); else mR0 = max2(mR0, v0);
        if (j < i1) mL1 = max2(mL1, v1); else mR1 = max2(mR1, v1);
        float2 c2 = cts[j+1], gb = gs_o[idx];
        float2 u0 = add2(c2, gb), u1 = add2(c2, ga);
        if (j+1 < i0) mL0 = max2(mL0, u0); else mR0 = max2(mR0, u0);
        if (j+1 < i1) mL1 = max2(mL1, u1); else mR1 = max2(mR1, u1);
        gprev = gb; idx++;
    }
    #pragma unroll 2
    for (; j + 1 <= 254; j += 2) {
        float2 c1 = cts[j],   ga = gs_e[idx];
        mR0 = max2(mR0, add2(c1, ga));
        mR1 = max2(mR1, add2(c1, gprev));
        float2 c2 = cts[j+1], gb = gs_o[idx];
        mR0 = max2(mR0, add2(c2, gb));
        mR1 = max2(mR1, add2(c2, ga));
        gprev = gb; idx++;
    }

    float2 z = make_float2(0.0f, 0.0f);
    if (t < 127) {
        float* p0 = d_pool + (b*S + i0)*(2*H) + 2*hp;
        *(float2*)(p0)     = max2(mL0, z);
        *(float2*)(p0 + H) = max2(mR0, z);
        float* p1 = d_pool + (b*S + i1)*(2*H) + 2*hp;
        *(float2*)(p1)     = max2(mL1, z);
        *(float2*)(p1 + H) = max2(mR1, z);
    }
}

// ---------------- final logits: warp per (b,s), transposed W ----------------
__global__ __launch_bounds__(256) void final_kernel(const float* fc_b, float* out) {
    int gw = (blockIdx.x * 256 + threadIdx.x) >> 5;   // 0..2047 = b*256+s
    int lane = threadIdx.x & 31;
    int s = gw & (S-1);
    float* o = out + gw * L;
    if (s == 0 || s == S-1) {
        o[lane] = 0.0f;
        if (lane < 2) o[lane + 32] = (lane == 1) ? 1.0f : 0.0f;
        return;
    }
    const float* pr = d_pool + gw * (2*H);
    const float* Wl = d_fcW2t + lane * 400;
    float a0 = 0.f, a1 = 0.f, a2 = 0.f, a3 = 0.f;
    #pragma unroll 4
    for (int c = 0; c < 400; c += 4) {
        float4 p = *(const float4*)(pr + c);
        float4 wv = *(const float4*)(Wl + c);
        a0 += p.x * wv.x; a1 += p.y * wv.y;
        a2 += p.z * wv.z; a3 += p.w * wv.w;
    }
    float acc0 = (a0 + a1) + (a2 + a3) + fc_b[lane];
    acc0 += d_Y[(gw-1)*NP + 600 + lane]
          + d_Y[gw*NP     + 634 + lane]
          + d_Y[(gw+1)*NP + 668 + lane];
    o[lane] = acc0;

    const float* W32 = d_fcW2t + 32 * 400;
    const float* W33 = d_fcW2t + 33 * 400;
    float r32 = 0.f, r33 = 0.f;
    #pragma unroll
    for (int c = lane; c < 400; c += 32) {
        float p = pr[c];
        r32 += p * W32[c];
        r33 += p * W33[c];
    }
    #pragma unroll
    for (int off = 16; off > 0; off >>= 1) {
        r32 += __shfl_xor_sync(0xFFFFFFFF, r32, off);
        r33 += __shfl_xor_sync(0xFFFFFFFF, r33, off);
    }
    if (lane < 2) {
        float r = (lane == 0) ? r32 : r33;
        r += fc_b[32 + lane]
           + d_Y[(gw-1)*NP + 632 + lane]
           + d_Y[gw*NP     + 666 + lane]
           + d_Y[(gw+1)*NP + 700 + lane];
        o[32 + lane] = r;
    }
}

extern "C" void kernel_launch(void* const* d_in, const int* in_sizes, int n_in,
                              void* d_out, int out_size) {
    const int*   inputs   = (const int*)d_in[0];
    const float* word_emb = (const float*)d_in[1];
    const float* pf_emb   = (const float*)d_in[2];
    const float* conv_W   = (const float*)d_in[3];
    const float* conv_b   = (const float*)d_in[4];
    const float* fc_W     = (const float*)d_in[5];
    const float* fc_b     = (const float*)d_in[6];
    float* out = (float*)d_out;

    gather_kernel<<<M, 320>>>(inputs, word_emb);          // launch 0
    pack_kernel<<<521, 256>>>(conv_W, fc_W, pf_emb);      // launch 1

    dim3 ggrid(M/128, NP/64);
    gemm_kernel<<<ggrid, 256>>>();                        // launch 2

    dim3 pgrid(H/2, B);
    pool_kernel<<<pgrid, 128>>>(conv_b);                  // launch 3 (profiled slot)

    final_kernel<<<256, 256>>>(fc_b, out);                // launch 4
}